// round 14
// baseline (speedup 1.0000x reference)
#include <cuda_runtime.h>
#include <cuda_fp16.h>
#include <mma.h>
using namespace nvcuda;

#define D 96
#define HP 96                              // fp16 row stride (192B = 6 sectors)
#define NMAX 50000
#define EMAX 800000
#define SCAN_B 512
#define NSCANBLK ((NMAX + SCAN_B - 1) / SCAN_B)   // 98
#define TM 64
#define LDH 104                            // half stride for staged tiles (pad 8)

// gemm smem: Whi,Wlo (96*LDH each) + Xhi,Xlo (TM*LDH each), halves
#define GEMM_SMEM_HALVES (2 * 96 * LDH + 2 * TM * LDH)
#define GEMM_SMEM_BYTES (GEMM_SMEM_HALVES * 2)

// ---------------- scratch (static device globals; no allocation) ----------
__device__ int    g_counts[NMAX];          // zero at load; re-zeroed by k_prep
__device__ int    g_rowptr[NMAX + 1];
__device__ int    g_cursor[NMAX];
__device__ float  g_dinv[NMAX];
__device__ int4   g_adj4[EMAX / 2 + 1];    // pairs of {src, bitcast(norm)}
__device__ __half g_hh[(size_t)NMAX * HP]; // GEMM out (fp16, unpadded rows)
__device__ float  g_h2[(size_t)NMAX * D];  // agg out / GEMM2 in (fp32)
__device__ int    g_blockSums[NSCANBLK + 2];
__device__ int    g_bar0, g_bar1, g_bar2;  // grid barriers (reset by agg1)

// ---------------- fused preprocessing: hist+scan+prefix+scatter ------------
// 98 blocks x 512 threads (all-resident on 148 SMs -> spin barriers safe).
__global__ __launch_bounds__(SCAN_B) void k_prep(const int* __restrict__ ei,
                                                 int n, int nb, int E) {
    __shared__ int wsum[16];
    __shared__ int sbase;
    int tidb = threadIdx.x;
    int i = blockIdx.x * SCAN_B + tidb;
    int lane = tidb & 31, wid = tidb >> 5;
    int gstride = nb * SCAN_B;

    // phase 0: degree histogram over edge destinations
    for (int e = blockIdx.x * SCAN_B + tidb; e < E; e += gstride)
        atomicAdd(&g_counts[ei[E + e]], 1);
    __threadfence();
    __syncthreads();
    if (tidb == 0) {
        atomicAdd(&g_bar0, 1);
        while (*(volatile int*)&g_bar0 < nb) { }
    }
    __syncthreads();

    // phase A: counts -> dinv, re-zero counts, block-local exclusive scan
    int v = 0;
    if (i < n) {
        v = g_counts[i];
        g_dinv[i] = rsqrtf((float)(v + 1));   // +1 self loop
        g_counts[i] = 0;                      // restore invariant for replay
    }
    int x = v;
#pragma unroll
    for (int o = 1; o < 32; o <<= 1) {
        int t = __shfl_up_sync(0xFFFFFFFFu, x, o);
        if (lane >= o) x += t;
    }
    if (lane == 31) wsum[wid] = x;
    __syncthreads();
    if (wid == 0) {
        int s = (lane < 16) ? wsum[lane] : 0;
#pragma unroll
        for (int o = 1; o < 16; o <<= 1) {
            int t = __shfl_up_sync(0xFFFFFFFFu, s, o);
            if (lane >= o) s += t;
        }
        if (lane < 16) wsum[lane] = s;
    }
    __syncthreads();
    int wbase = (wid > 0) ? wsum[wid - 1] : 0;
    if (i < n) g_rowptr[i] = wbase + x - v;          // block-local exclusive
    if (tidb == SCAN_B - 1) g_blockSums[blockIdx.x] = wbase + x;
    __threadfence();
    __syncthreads();
    if (tidb == 0) {
        atomicAdd(&g_bar1, 1);
        while (*(volatile int*)&g_bar1 < nb) { }
    }
    __syncthreads();

    // phase B: cross-block prefix, finalize rowptr + cursor
    if (wid == 0) {
        int acc = 0;
        for (int b = lane; b < blockIdx.x; b += 32) acc += g_blockSums[b];
#pragma unroll
        for (int o = 16; o; o >>= 1) acc += __shfl_xor_sync(0xFFFFFFFFu, acc, o);
        if (lane == 0) sbase = acc;
    }
    __syncthreads();
    int rbase = sbase;
    if (i < n) {
        int val = g_rowptr[i] + rbase;
        g_rowptr[i] = val;
        g_cursor[i] = val;
    }
    if (blockIdx.x == nb - 1 && tidb == 0)
        g_rowptr[n] = rbase + g_blockSums[nb - 1];   // total = E
    __threadfence();
    __syncthreads();
    if (tidb == 0) {
        atomicAdd(&g_bar2, 1);
        while (*(volatile int*)&g_bar2 < nb) { }
    }
    __syncthreads();

    // phase C: scatter edges into CSR
    int2* adj = (int2*)g_adj4;
    for (int e = blockIdx.x * SCAN_B + tidb; e < E; e += gstride) {
        int s = ei[e];
        int d = ei[E + e];
        int pos = atomicAdd(&g_cursor[d], 1);
        float norm = g_dinv[s] * g_dinv[d];
        adj[pos] = make_int2(s, __float_as_int(norm));
    }
}

// ---------------- tensor-core GEMM: Hh[N,HP] = X[N,96] @ W[96,96] ----------
// Split-fp16 compensated HMMA: X=Xhi+Xlo, W=Whi+Wlo (fp16 residual split);
// acc += Xhi*Whi + Xhi*Wlo + Xlo*Whi (fp32 accum) -> fp32-class accuracy.
// block: 256 threads (8 warps), TM=64 rows. warp w -> m-tile w&3, n-tiles
// (w>>2)*3 + {0,1,2} of 16x16. Output staged via smem overlay -> fp16 g_hh.
__global__ __launch_bounds__(256) void k_gemm(const float* __restrict__ Xext,
                                              const float* __restrict__ W,
                                              int n, int src_sel) {
    extern __shared__ __align__(16) __half sm[];
    __half* Whi = sm;
    __half* Wlo = Whi + 96 * LDH;
    __half* Xhi = Wlo + 96 * LDH;
    __half* Xlo = Xhi + TM * LDH;
    float*  Os  = (float*)Xhi;              // overlay after compute

    const float* X = src_sel ? (const float*)g_h2 : Xext;
    int tid = threadIdx.x;

    // stage W split (fp32 -> hi fp16 + residual fp16)
    for (int i = tid; i < 96 * 96; i += 256) {
        int r = i / 96, c = i % 96;
        float v = W[i];
        __half h = __float2half_rn(v);
        Whi[r * LDH + c] = h;
        Wlo[r * LDH + c] = __float2half_rn(v - __half2float(h));
    }
    // stage X split
    int n0 = blockIdx.x * TM;
    int rows = min(TM, n - n0);
    for (int i = tid; i < TM * 96; i += 256) {
        int r = i / 96, c = i % 96;
        float v = (r < rows) ? X[(size_t)(n0 + r) * 96 + c] : 0.f;
        __half h = __float2half_rn(v);
        Xhi[r * LDH + c] = h;
        Xlo[r * LDH + c] = __float2half_rn(v - __half2float(h));
    }
    __syncthreads();

    int warp = tid >> 5;
    int mi = warp & 3;                      // m tile 0..3
    int ng = warp >> 2;                     // n group 0..1 -> tiles ng*3+{0,1,2}

    wmma::fragment<wmma::accumulator, 16, 16, 16, float> acc[3];
#pragma unroll
    for (int j = 0; j < 3; j++) wmma::fill_fragment(acc[j], 0.f);

#pragma unroll
    for (int k = 0; k < 96; k += 16) {
        wmma::fragment<wmma::matrix_a, 16, 16, 16, __half, wmma::row_major> ahi, alo;
        wmma::load_matrix_sync(ahi, &Xhi[(mi * 16) * LDH + k], LDH);
        wmma::load_matrix_sync(alo, &Xlo[(mi * 16) * LDH + k], LDH);
#pragma unroll
        for (int j = 0; j < 3; j++) {
            int nn = (ng * 3 + j) * 16;
            wmma::fragment<wmma::matrix_b, 16, 16, 16, __half, wmma::row_major> bhi, blo;
            wmma::load_matrix_sync(bhi, &Whi[k * LDH + nn], LDH);
            wmma::load_matrix_sync(blo, &Wlo[k * LDH + nn], LDH);
            wmma::mma_sync(acc[j], ahi, bhi, acc[j]);
            wmma::mma_sync(acc[j], ahi, blo, acc[j]);
            wmma::mma_sync(acc[j], alo, bhi, acc[j]);
        }
    }
    __syncthreads();                        // X tiles no longer needed

    // store accumulators to smem (fp32, ld=96), then convert to fp16 global
#pragma unroll
    for (int j = 0; j < 3; j++) {
        int nn = (ng * 3 + j) * 16;
        wmma::store_matrix_sync(&Os[(mi * 16) * 96 + nn], acc[j], 96,
                                wmma::mem_row_major);
    }
    __syncthreads();

    union H4 { __half2 h2[4]; uint4 u; };
    for (int i = tid; i < TM * 12; i += 256) {   // 12 groups of 8 floats per row
        int r = i / 12, g = i % 12;
        if (r < rows) {
            const float* src = &Os[r * 96 + g * 8];
            H4 s;
            s.h2[0] = __floats2half2_rn(src[0], src[1]);
            s.h2[1] = __floats2half2_rn(src[2], src[3]);
            s.h2[2] = __floats2half2_rn(src[4], src[5]);
            s.h2[3] = __floats2half2_rn(src[6], src[7]);
            *(uint4*)&g_hh[(size_t)(n0 + r) * HP + g * 8] = s.u;
        }
    }
}

// ---------------- aggregation: one warp per node ---------------------------
// reads g_hh (fp16, 192B rows = 6 sectors); writes g_h2 or out.
// lane L (<24) handles features 4L..4L+3 via one LDG.64; lanes 24-31 idle.
// adj int4 = 2 edges per broadcast LDG.128. 4-edge unrolled for MLP.
__global__ __launch_bounds__(256) void k_agg(const float* __restrict__ bias,
                                             const float* __restrict__ aptr,
                                             float* __restrict__ outExt,
                                             int n, int do_prelu, int dst_sel,
                                             int reset_bar) {
    if (reset_bar && blockIdx.x == 0 && threadIdx.x == 0) {
        g_bar0 = 0; g_bar1 = 0; g_bar2 = 0;   // for next replay's k_prep
    }
    int warp = (blockIdx.x * blockDim.x + threadIdx.x) >> 5;
    int lane = threadIdx.x & 31;
    if (warp >= n) return;

    const __half* h = (const __half*)g_hh;
    float* out = dst_sel ? outExt : (float*)g_h2;
    bool active = lane < 24;
    const uint2 zz = make_uint2(0u, 0u);

    float dn = g_dinv[warp];
    float dn2 = dn * dn;

    uint2 su = active ? *(const uint2*)(h + (size_t)warp * HP + lane * 4) : zz;
    float2 sp0 = __half22float2(*(__half2*)&su.x);
    float2 sp1 = __half22float2(*(__half2*)&su.y);
    float a0 = sp0.x * dn2, a1 = sp0.y * dn2;
    float a2 = sp1.x * dn2, a3 = sp1.y * dn2;

    int e = g_rowptr[warp];
    int end = g_rowptr[warp + 1];
    const int2* adj = (const int2*)g_adj4;

    if ((e & 1) && e < end) {                 // align to int4 pairs
        int2 q = adj[e];
        float nn = __int_as_float(q.y);
        uint2 u = active ? *(const uint2*)(h + (size_t)q.x * HP + lane * 4) : zz;
        float2 p0 = __half22float2(*(__half2*)&u.x);
        float2 p1 = __half22float2(*(__half2*)&u.y);
        a0 = fmaf(p0.x, nn, a0); a1 = fmaf(p0.y, nn, a1);
        a2 = fmaf(p1.x, nn, a2); a3 = fmaf(p1.y, nn, a3);
        e++;
    }
    for (; e + 3 < end; e += 4) {             // 4 edges: 2 adj LDG.128 + 4 LDG.64
        int4 qa = *(const int4*)(adj + e);
        int4 qb = *(const int4*)(adj + e + 2);
        uint2 u0 = active ? *(const uint2*)(h + (size_t)qa.x * HP + lane * 4) : zz;
        uint2 u1 = active ? *(const uint2*)(h + (size_t)qa.z * HP + lane * 4) : zz;
        uint2 u2 = active ? *(const uint2*)(h + (size_t)qb.x * HP + lane * 4) : zz;
        uint2 u3 = active ? *(const uint2*)(h + (size_t)qb.z * HP + lane * 4) : zz;
        float n0 = __int_as_float(qa.y), n1 = __int_as_float(qa.w);
        float n2 = __int_as_float(qb.y), n3 = __int_as_float(qb.w);
        float2 p00 = __half22float2(*(__half2*)&u0.x);
        float2 p01 = __half22float2(*(__half2*)&u0.y);
        float2 p10 = __half22float2(*(__half2*)&u1.x);
        float2 p11 = __half22float2(*(__half2*)&u1.y);
        float2 p20 = __half22float2(*(__half2*)&u2.x);
        float2 p21 = __half22float2(*(__half2*)&u2.y);
        float2 p30 = __half22float2(*(__half2*)&u3.x);
        float2 p31 = __half22float2(*(__half2*)&u3.y);
        a0 = fmaf(p00.x, n0, a0); a1 = fmaf(p00.y, n0, a1);
        a2 = fmaf(p01.x, n0, a2); a3 = fmaf(p01.y, n0, a3);
        a0 = fmaf(p10.x, n1, a0); a1 = fmaf(p10.y, n1, a1);
        a2 = fmaf(p11.x, n1, a2); a3 = fmaf(p11.y, n1, a3);
        a0 = fmaf(p20.x, n2, a0); a1 = fmaf(p20.y, n2, a1);
        a2 = fmaf(p21.x, n2, a2); a3 = fmaf(p21.y, n2, a3);
        a0 = fmaf(p30.x, n3, a0); a1 = fmaf(p30.y, n3, a1);
        a2 = fmaf(p31.x, n3, a2); a3 = fmaf(p31.y, n3, a3);
    }
    for (; e + 1 < end; e += 2) {
        int4 q = *(const int4*)(adj + e);
        uint2 u0 = active ? *(const uint2*)(h + (size_t)q.x * HP + lane * 4) : zz;
        uint2 u1 = active ? *(const uint2*)(h + (size_t)q.z * HP + lane * 4) : zz;
        float n0 = __int_as_float(q.y), n1 = __int_as_float(q.w);
        float2 p00 = __half22float2(*(__half2*)&u0.x);
        float2 p01 = __half22float2(*(__half2*)&u0.y);
        float2 p10 = __half22float2(*(__half2*)&u1.x);
        float2 p11 = __half22float2(*(__half2*)&u1.y);
        a0 = fmaf(p00.x, n0, a0); a1 = fmaf(p00.y, n0, a1);
        a2 = fmaf(p01.x, n0, a2); a3 = fmaf(p01.y, n0, a3);
        a0 = fmaf(p10.x, n1, a0); a1 = fmaf(p10.y, n1, a1);
        a2 = fmaf(p11.x, n1, a2); a3 = fmaf(p11.y, n1, a3);
    }
    if (e < end) {
        int2 q = adj[e];
        float nn = __int_as_float(q.y);
        uint2 u = active ? *(const uint2*)(h + (size_t)q.x * HP + lane * 4) : zz;
        float2 p0 = __half22float2(*(__half2*)&u.x);
        float2 p1 = __half22float2(*(__half2*)&u.y);
        a0 = fmaf(p0.x, nn, a0); a1 = fmaf(p0.y, nn, a1);
        a2 = fmaf(p1.x, nn, a2); a3 = fmaf(p1.y, nn, a3);
    }

    if (active) {                             // features 4L..4L+3 valid
        float4 bb = ((const float4*)bias)[lane];
        a0 += bb.x; a1 += bb.y; a2 += bb.z; a3 += bb.w;
        if (do_prelu) {
            float a = aptr[0];
            a0 = (a0 > 0.f) ? a0 : a * a0;
            a1 = (a1 > 0.f) ? a1 : a * a1;
            a2 = (a2 > 0.f) ? a2 : a * a2;
            a3 = (a3 > 0.f) ? a3 : a * a3;
        }
        ((float4*)(out + (size_t)warp * 96))[lane] = make_float4(a0, a1, a2, a3);
    }
}

// ---------------- launch ---------------------------------------------------
extern "C" void kernel_launch(void* const* d_in, const int* in_sizes, int n_in,
                              void* d_out, int out_size) {
    const float* x  = (const float*)d_in[0];
    const int*   ei = (const int*)d_in[1];      // int32! (JAX x64 disabled)
    const float* W1 = (const float*)d_in[2];
    const float* b1 = (const float*)d_in[3];
    const float* a1 = (const float*)d_in[4];
    const float* W2 = (const float*)d_in[5];
    const float* b2 = (const float*)d_in[6];
    float*       out = (float*)d_out;

    int N = in_sizes[0] / D;
    int E = in_sizes[1] / 2;

    int nscan = (N + SCAN_B - 1) / SCAN_B;
    int gemm_blocks = (N + TM - 1) / TM;
    int agg_blocks = (N * 32 + 255) / 256;

    cudaFuncSetAttribute(k_gemm, cudaFuncAttributeMaxDynamicSharedMemorySize,
                         GEMM_SMEM_BYTES);

    // 1) GEMM1 (tensor cores)
    k_gemm<<<gemm_blocks, 256, GEMM_SMEM_BYTES>>>(x, W1, N, 0);
    // 2) fused preprocessing: hist + scan + prefix + scatter (one launch)
    k_prep<<<nscan, SCAN_B>>>(ei, N, nscan, E);
    // 3) layer-1 aggregate + PReLU -> g_h2 (also resets barrier counters)
    k_agg<<<agg_blocks, 256>>>(b1, a1, out, N, 1, 0, 1);
    // 4) GEMM2: g_h2 @ W2 -> g_hh
    k_gemm<<<gemm_blocks, 256, GEMM_SMEM_BYTES>>>(x /*unused*/, W2, N, 1);
    // 5) layer-2 aggregate -> out
    k_agg<<<agg_blocks, 256>>>(b2, a1, out, N, 0, 1, 0);
}

// round 15
// speedup vs baseline: 1.0858x; 1.0858x over previous
#include <cuda_runtime.h>
#include <cuda_fp16.h>
#include <mma.h>
using namespace nvcuda;

#define D 96
#define HP 96                              // fp16 row stride (192B = 6 sectors)
#define NMAX 50000
#define EMAX 800000
#define SCAN_B 512
#define NSCANBLK ((NMAX + SCAN_B - 1) / SCAN_B)   // 98
#define TM 64
#define LDH 104                            // half stride for staged tiles (pad 8)

// gemm smem: Whi,Wlo (96*LDH each) + Xhi,Xlo (TM*LDH each), halves
#define GEMM_SMEM_HALVES (2 * 96 * LDH + 2 * TM * LDH)
#define GEMM_SMEM_BYTES (GEMM_SMEM_HALVES * 2)

// ---------------- scratch (static device globals; no allocation) ----------
__device__ int    g_counts[NMAX];          // zero at load; re-zeroed by k_scan1
__device__ int    g_rowptr[NMAX + 1];
__device__ int    g_cursor[NMAX];
__device__ float  g_dinv[NMAX];
__device__ int4   g_adj4[EMAX / 2 + 1];    // pairs of {src, bitcast(norm)}
__device__ __half g_hh[(size_t)NMAX * HP]; // GEMM out (fp16, unpadded rows)
__device__ __half g_Xhi[(size_t)NMAX * D]; // GEMM input hi (fp16)
__device__ __half g_Xlo[(size_t)NMAX * D]; // GEMM input lo residual (fp16)
__device__ __half g_Whl[2][2 * 96 * LDH];  // prestaged W splits, LDH-strided
__device__ int    g_blockSums[NSCANBLK + 2];

// ---------------- input/weight split (runs once per launch) ----------------
// splits X (fp32 -> hi/lo fp16, packed stride 96) and W1/W2 (LDH-strided).
__global__ void k_split(const float* __restrict__ x,
                        const float* __restrict__ W1,
                        const float* __restrict__ W2, int n) {
    int i = blockIdx.x * blockDim.x + threadIdx.x;
    int totalX = n * D;
    if (i < totalX) {
        float v = x[i];
        __half h = __float2half_rn(v);
        g_Xhi[i] = h;
        g_Xlo[i] = __float2half_rn(v - __half2float(h));
    }
    if (i < 2 * 96 * 96) {
        int l = i / (96 * 96), j = i % (96 * 96);
        int r = j / 96, c = j % 96;
        float v = (l ? W2 : W1)[j];
        __half h = __float2half_rn(v);
        g_Whl[l][r * LDH + c] = h;
        g_Whl[l][96 * LDH + r * LDH + c] = __float2half_rn(v - __half2float(h));
    }
}

// ---------------- graph preprocessing (round-13 proven structure) ----------
__global__ void k_hist(const int* __restrict__ ei, int E) {
    int e = blockIdx.x * blockDim.x + threadIdx.x;
    if (e < E) atomicAdd(&g_counts[ei[E + e]], 1);
}

__global__ void k_scan1(int n) {
    __shared__ int wsum[16];
    int i = blockIdx.x * SCAN_B + threadIdx.x;
    int lane = threadIdx.x & 31, wid = threadIdx.x >> 5;
    int v = 0;
    if (i < n) {
        v = g_counts[i];
        g_dinv[i] = rsqrtf((float)(v + 1));   // +1 self loop
        g_counts[i] = 0;                      // restore invariant for replay
    }
    int x = v;
#pragma unroll
    for (int o = 1; o < 32; o <<= 1) {
        int t = __shfl_up_sync(0xFFFFFFFFu, x, o);
        if (lane >= o) x += t;
    }
    if (lane == 31) wsum[wid] = x;
    __syncthreads();
    if (wid == 0) {
        int s = (lane < 16) ? wsum[lane] : 0;
#pragma unroll
        for (int o = 1; o < 16; o <<= 1) {
            int t = __shfl_up_sync(0xFFFFFFFFu, s, o);
            if (lane >= o) s += t;
        }
        if (lane < 16) wsum[lane] = s;
    }
    __syncthreads();
    int base = (wid > 0) ? wsum[wid - 1] : 0;
    if (i < n) g_rowptr[i] = base + x - v;           // exclusive (block-local)
    if (threadIdx.x == SCAN_B - 1) g_blockSums[blockIdx.x] = base + x;
}

__global__ void k_scan3(int n, int nb) {
    __shared__ int sbase;
    int bid = blockIdx.x;
    if (threadIdx.x < 32) {
        int lane = threadIdx.x;
        int acc = 0;
        for (int b = lane; b < bid; b += 32) acc += g_blockSums[b];
#pragma unroll
        for (int o = 16; o; o >>= 1) acc += __shfl_xor_sync(0xFFFFFFFFu, acc, o);
        if (lane == 0) sbase = acc;
    }
    __syncthreads();
    int base = sbase;
    int i = bid * SCAN_B + threadIdx.x;
    if (i < n) {
        int v = g_rowptr[i] + base;
        g_rowptr[i] = v;
        g_cursor[i] = v;
    }
    if (bid == nb - 1 && threadIdx.x == 0) {
        int tot = base;
        for (int b = bid; b < nb; b++) tot += g_blockSums[b];
        g_rowptr[n] = tot;                   // total = E
    }
}

__global__ void k_scatter(const int* __restrict__ ei, int E) {
    int e = blockIdx.x * blockDim.x + threadIdx.x;
    if (e < E) {
        int s = ei[e];
        int d = ei[E + e];
        int pos = atomicAdd(&g_cursor[d], 1);
        float norm = g_dinv[s] * g_dinv[d];
        ((int2*)g_adj4)[pos] = make_int2(s, __float_as_int(norm));
    }
}

// ---------------- tensor-core GEMM: Hh[N,96] = X[N,96] @ W[96,96] ----------
// Split-fp16 compensated HMMA on PRESTAGED hi/lo operands (pure-copy staging):
// acc += Xhi*Whi + Xhi*Wlo + Xlo*Whi (fp32 accum) -> fp32-class accuracy.
// block: 256 threads (8 warps), TM=64 rows. warp w -> m-tile w&3, n-tiles
// (w>>2)*3 + {0,1,2} of 16x16. Output staged via smem overlay -> fp16 g_hh.
__global__ __launch_bounds__(256) void k_gemm(int n, int layer) {
    extern __shared__ __align__(16) __half sm[];
    __half* Whi = sm;                       // hi+lo contiguous, same as global
    __half* Xhi = Whi + 2 * 96 * LDH;
    __half* Xlo = Xhi + TM * LDH;
    float*  Os  = (float*)Xhi;              // overlay after compute

    int tid = threadIdx.x;
    int n0 = blockIdx.x * TM;
    int rows = min(TM, n - n0);

    // stage W: straight uint4 copy of prestaged hi+lo (no conversions)
    {
        const uint4* s = (const uint4*)g_Whl[layer];
        uint4* d = (uint4*)Whi;
        for (int i = tid; i < (2 * 96 * LDH) / 8; i += 256) d[i] = s[i];
    }
    // stage X: row-wise uint4 copies from packed hi/lo (no conversions)
    {
        const uint4 zz = make_uint4(0, 0, 0, 0);
        for (int i = tid; i < TM * 12; i += 256) {
            int r = i / 12, c = (i % 12) * 8;
            uint4 vh = zz, vl = zz;
            if (r < rows) {
                vh = *(const uint4*)&g_Xhi[(size_t)(n0 + r) * 96 + c];
                vl = *(const uint4*)&g_Xlo[(size_t)(n0 + r) * 96 + c];
            }
            *(uint4*)&Xhi[r * LDH + c] = vh;
            *(uint4*)&Xlo[r * LDH + c] = vl;
        }
    }
    __syncthreads();

    int warp = tid >> 5;
    int mi = warp & 3;                      // m tile 0..3
    int ng = warp >> 2;                     // n group 0..1 -> tiles ng*3+{0,1,2}
    __half* Wlo = Whi + 96 * LDH;

    wmma::fragment<wmma::accumulator, 16, 16, 16, float> acc[3];
#pragma unroll
    for (int j = 0; j < 3; j++) wmma::fill_fragment(acc[j], 0.f);

#pragma unroll
    for (int k = 0; k < 96; k += 16) {
        wmma::fragment<wmma::matrix_a, 16, 16, 16, __half, wmma::row_major> ahi, alo;
        wmma::load_matrix_sync(ahi, &Xhi[(mi * 16) * LDH + k], LDH);
        wmma::load_matrix_sync(alo, &Xlo[(mi * 16) * LDH + k], LDH);
#pragma unroll
        for (int j = 0; j < 3; j++) {
            int nn = (ng * 3 + j) * 16;
            wmma::fragment<wmma::matrix_b, 16, 16, 16, __half, wmma::row_major> bhi, blo;
            wmma::load_matrix_sync(bhi, &Whi[k * LDH + nn], LDH);
            wmma::load_matrix_sync(blo, &Wlo[k * LDH + nn], LDH);
            wmma::mma_sync(acc[j], ahi, bhi, acc[j]);
            wmma::mma_sync(acc[j], ahi, blo, acc[j]);
            wmma::mma_sync(acc[j], alo, bhi, acc[j]);
        }
    }
    __syncthreads();                        // X tiles no longer needed

#pragma unroll
    for (int j = 0; j < 3; j++) {
        int nn = (ng * 3 + j) * 16;
        wmma::store_matrix_sync(&Os[(mi * 16) * 96 + nn], acc[j], 96,
                                wmma::mem_row_major);
    }
    __syncthreads();

    union H4 { __half2 h2[4]; uint4 u; };
    for (int i = tid; i < TM * 12; i += 256) {   // 12 groups of 8 floats per row
        int r = i / 12, g = i % 12;
        if (r < rows) {
            const float* src = &Os[r * 96 + g * 8];
            H4 s;
            s.h2[0] = __floats2half2_rn(src[0], src[1]);
            s.h2[1] = __floats2half2_rn(src[2], src[3]);
            s.h2[2] = __floats2half2_rn(src[4], src[5]);
            s.h2[3] = __floats2half2_rn(src[6], src[7]);
            *(uint4*)&g_hh[(size_t)(n0 + r) * HP + g * 8] = s.u;
        }
    }
}

// ---------------- aggregation: one warp per node ---------------------------
// reads g_hh (fp16, 192B rows); dst_sel=0: writes hi/lo split (GEMM2 input),
// dst_sel=1: writes external fp32 out. lane L (<24) owns features 4L..4L+3.
__global__ __launch_bounds__(256) void k_agg(const float* __restrict__ bias,
                                             const float* __restrict__ aptr,
                                             float* __restrict__ outExt,
                                             int n, int do_prelu, int dst_sel) {
    int warp = (blockIdx.x * blockDim.x + threadIdx.x) >> 5;
    int lane = threadIdx.x & 31;
    if (warp >= n) return;

    const __half* h = (const __half*)g_hh;
    bool active = lane < 24;
    const uint2 zz = make_uint2(0u, 0u);

    float dn = g_dinv[warp];
    float dn2 = dn * dn;

    uint2 su = active ? *(const uint2*)(h + (size_t)warp * HP + lane * 4) : zz;
    float2 sp0 = __half22float2(*(__half2*)&su.x);
    float2 sp1 = __half22float2(*(__half2*)&su.y);
    float a0 = sp0.x * dn2, a1 = sp0.y * dn2;
    float a2 = sp1.x * dn2, a3 = sp1.y * dn2;

    int e = g_rowptr[warp];
    int end = g_rowptr[warp + 1];
    const int2* adj = (const int2*)g_adj4;

    if ((e & 1) && e < end) {                 // align to int4 pairs
        int2 q = adj[e];
        float nn = __int_as_float(q.y);
        uint2 u = active ? *(const uint2*)(h + (size_t)q.x * HP + lane * 4) : zz;
        float2 p0 = __half22float2(*(__half2*)&u.x);
        float2 p1 = __half22float2(*(__half2*)&u.y);
        a0 = fmaf(p0.x, nn, a0); a1 = fmaf(p0.y, nn, a1);
        a2 = fmaf(p1.x, nn, a2); a3 = fmaf(p1.y, nn, a3);
        e++;
    }
    for (; e + 3 < end; e += 4) {             // 4 edges: 2 adj LDG.128 + 4 LDG.64
        int4 qa = *(const int4*)(adj + e);
        int4 qb = *(const int4*)(adj + e + 2);
        uint2 u0 = active ? *(const uint2*)(h + (size_t)qa.x * HP + lane * 4) : zz;
        uint2 u1 = active ? *(const uint2*)(h + (size_t)qa.z * HP + lane * 4) : zz;
        uint2 u2 = active ? *(const uint2*)(h + (size_t)qb.x * HP + lane * 4) : zz;
        uint2 u3 = active ? *(const uint2*)(h + (size_t)qb.z * HP + lane * 4) : zz;
        float n0 = __int_as_float(qa.y), n1 = __int_as_float(qa.w);
        float n2 = __int_as_float(qb.y), n3 = __int_as_float(qb.w);
        float2 p00 = __half22float2(*(__half2*)&u0.x);
        float2 p01 = __half22float2(*(__half2*)&u0.y);
        float2 p10 = __half22float2(*(__half2*)&u1.x);
        float2 p11 = __half22float2(*(__half2*)&u1.y);
        float2 p20 = __half22float2(*(__half2*)&u2.x);
        float2 p21 = __half22float2(*(__half2*)&u2.y);
        float2 p30 = __half22float2(*(__half2*)&u3.x);
        float2 p31 = __half22float2(*(__half2*)&u3.y);
        a0 = fmaf(p00.x, n0, a0); a1 = fmaf(p00.y, n0, a1);
        a2 = fmaf(p01.x, n0, a2); a3 = fmaf(p01.y, n0, a3);
        a0 = fmaf(p10.x, n1, a0); a1 = fmaf(p10.y, n1, a1);
        a2 = fmaf(p11.x, n1, a2); a3 = fmaf(p11.y, n1, a3);
        a0 = fmaf(p20.x, n2, a0); a1 = fmaf(p20.y, n2, a1);
        a2 = fmaf(p21.x, n2, a2); a3 = fmaf(p21.y, n2, a3);
        a0 = fmaf(p30.x, n3, a0); a1 = fmaf(p30.y, n3, a1);
        a2 = fmaf(p31.x, n3, a2); a3 = fmaf(p31.y, n3, a3);
    }
    for (; e + 1 < end; e += 2) {
        int4 q = *(const int4*)(adj + e);
        uint2 u0 = active ? *(const uint2*)(h + (size_t)q.x * HP + lane * 4) : zz;
        uint2 u1 = active ? *(const uint2*)(h + (size_t)q.z * HP + lane * 4) : zz;
        float n0 = __int_as_float(q.y), n1 = __int_as_float(q.w);
        float2 p00 = __half22float2(*(__half2*)&u0.x);
        float2 p01 = __half22float2(*(__half2*)&u0.y);
        float2 p10 = __half22float2(*(__half2*)&u1.x);
        float2 p11 = __half22float2(*(__half2*)&u1.y);
        a0 = fmaf(p00.x, n0, a0); a1 = fmaf(p00.y, n0, a1);
        a2 = fmaf(p01.x, n0, a2); a3 = fmaf(p01.y, n0, a3);
        a0 = fmaf(p10.x, n1, a0); a1 = fmaf(p10.y, n1, a1);
        a2 = fmaf(p11.x, n1, a2); a3 = fmaf(p11.y, n1, a3);
    }
    if (e < end) {
        int2 q = adj[e];
        float nn = __int_as_float(q.y);
        uint2 u = active ? *(const uint2*)(h + (size_t)q.x * HP + lane * 4) : zz;
        float2 p0 = __half22float2(*(__half2*)&u.x);
        float2 p1 = __half22float2(*(__half2*)&u.y);
        a0 = fmaf(p0.x, nn, a0); a1 = fmaf(p0.y, nn, a1);
        a2 = fmaf(p1.x, nn, a2); a3 = fmaf(p1.y, nn, a3);
    }

    if (active) {                             // features 4L..4L+3 valid
        float4 bb = ((const float4*)bias)[lane];
        a0 += bb.x; a1 += bb.y; a2 += bb.z; a3 += bb.w;
        if (do_prelu) {
            float a = aptr[0];
            a0 = (a0 > 0.f) ? a0 : a * a0;
            a1 = (a1 > 0.f) ? a1 : a * a1;
            a2 = (a2 > 0.f) ? a2 : a * a2;
            a3 = (a3 > 0.f) ? a3 : a * a3;
        }
        if (dst_sel) {
            ((float4*)(outExt + (size_t)warp * 96))[lane] =
                make_float4(a0, a1, a2, a3);
        } else {
            // write hi/lo fp16 split (GEMM2 input) — same split GEMM2 staging
            // used to compute from fp32, so precision is identical.
            __half2 H0 = __floats2half2_rn(a0, a1);
            __half2 H1 = __floats2half2_rn(a2, a3);
            float2 b0 = __half22float2(H0);
            float2 b1 = __half22float2(H1);
            __half2 L0 = __floats2half2_rn(a0 - b0.x, a1 - b0.y);
            __half2 L1 = __floats2half2_rn(a2 - b1.x, a3 - b1.y);
            size_t off = (size_t)warp * 96 + lane * 4;
            *(uint2*)&g_Xhi[off] = make_uint2(*(unsigned*)&H0, *(unsigned*)&H1);
            *(uint2*)&g_Xlo[off] = make_uint2(*(unsigned*)&L0, *(unsigned*)&L1);
        }
    }
}

// ---------------- launch ---------------------------------------------------
extern "C" void kernel_launch(void* const* d_in, const int* in_sizes, int n_in,
                              void* d_out, int out_size) {
    const float* x  = (const float*)d_in[0];
    const int*   ei = (const int*)d_in[1];      // int32! (JAX x64 disabled)
    const float* W1 = (const float*)d_in[2];
    const float* b1 = (const float*)d_in[3];
    const float* a1 = (const float*)d_in[4];
    const float* W2 = (const float*)d_in[5];
    const float* b2 = (const float*)d_in[6];
    float*       out = (float*)d_out;

    int N = in_sizes[0] / D;
    int E = in_sizes[1] / 2;

    int nscan = (N + SCAN_B - 1) / SCAN_B;
    int gemm_blocks = (N + TM - 1) / TM;
    int agg_blocks = (N * 32 + 255) / 256;
    int split_work = N * D;                 // >= 2*96*96 always (N >= 192)
    int split_blocks = (split_work + 255) / 256;

    cudaFuncSetAttribute(k_gemm, cudaFuncAttributeMaxDynamicSharedMemorySize,
                         GEMM_SMEM_BYTES);

    // 1) split X, W1, W2 into hi/lo fp16 (once; replay-deterministic)
    k_split<<<split_blocks, 256>>>(x, W1, W2, N);
    // 2) GEMM1 (tensor cores, pure-copy staging)
    k_gemm<<<gemm_blocks, 256, GEMM_SMEM_BYTES>>>(N, 0);
    // 3-6) graph preprocessing
    k_hist<<<(E + 255) / 256, 256>>>(ei, E);
    k_scan1<<<nscan, SCAN_B>>>(N);
    k_scan3<<<nscan, SCAN_B>>>(N, nscan);
    k_scatter<<<(E + 255) / 256, 256>>>(ei, E);
    // 7) layer-1 aggregate + PReLU -> hi/lo split (GEMM2 input)
    k_agg<<<agg_blocks, 256>>>(b1, a1, out, N, 1, 0);
    // 8) GEMM2
    k_gemm<<<gemm_blocks, 256, GEMM_SMEM_BYTES>>>(N, 1);
    // 9) layer-2 aggregate -> out
    k_agg<<<agg_blocks, 256>>>(b2, a1, out, N, 0, 1);
}

// round 17
// speedup vs baseline: 1.1604x; 1.0686x over previous
#include <cuda_runtime.h>
#include <cuda_fp16.h>
#include <mma.h>
using namespace nvcuda;

#define D 96
#define HP 96                              // fp16 row stride (192B = 6 sectors)
#define NMAX 50000
#define EMAX 800000
#define SCAN_B 512
#define NSCANBLK ((NMAX + SCAN_B - 1) / SCAN_B)   // 98
#define TM 64
#define LDH 104                            // half stride for staged tiles (pad 8)

// gemm smem: Whi,Wlo (96*LDH each) + Xhi (TM*LDH), halves
#define GEMM_SMEM_HALVES (2 * 96 * LDH + TM * LDH)
#define GEMM_SMEM_BYTES (GEMM_SMEM_HALVES * 2)    // 53248

// ---------------- scratch (static device globals; no allocation) ----------
__device__ int    g_counts[NMAX];          // zero at load; re-zeroed by k_scan
__device__ int    g_rowptr[NMAX + 1];
__device__ int    g_cursor[NMAX];
__device__ float  g_dinv[NMAX];
__device__ int4   g_adj4[EMAX / 2 + 1];    // pairs of {src, bitcast(norm)}
__device__ __half g_hh[(size_t)NMAX * HP]; // GEMM out (fp16, unpadded rows)
__device__ __half g_Xhi[(size_t)NMAX * D]; // GEMM input (fp16)
__device__ __half g_Whl[2][2 * 96 * LDH];  // prestaged W hi+lo, LDH-strided
__device__ unsigned long long g_status[NSCANBLK]; // lookback; reset by agg1

// ---------------- split X/W + degree histogram (one kernel) ----------------
__global__ void k_split(const float* __restrict__ x,
                        const float* __restrict__ W1,
                        const float* __restrict__ W2,
                        const int* __restrict__ ei, int n, int E) {
    int i = blockIdx.x * blockDim.x + threadIdx.x;
    if (i < n * D) g_Xhi[i] = __float2half_rn(x[i]);
    if (i < 2 * 96 * 96) {
        int l = i / (96 * 96), j = i % (96 * 96);
        int r = j / 96, c = j % 96;
        float v = (l ? W2 : W1)[j];
        __half h = __float2half_rn(v);
        g_Whl[l][r * LDH + c] = h;
        g_Whl[l][96 * LDH + r * LDH + c] = __float2half_rn(v - __half2float(h));
    }
    int stride = gridDim.x * blockDim.x;
    for (int e = i; e < E; e += stride)
        atomicAdd(&g_counts[ei[E + e]], 1);
}

// ---------------- single-pass scan (decoupled lookback) --------------------
// fuses: dinv, counts re-zero, exclusive scan -> rowptr + cursor.
// state: 0=invalid, 1=aggregate, 2=inclusive prefix; low 32 bits = value.
__global__ __launch_bounds__(SCAN_B) void k_scan(int n, int nb) {
    __shared__ int wsum[16];
    __shared__ int sbase;
    int tidb = threadIdx.x, b = blockIdx.x;
    int i = b * SCAN_B + tidb;
    int lane = tidb & 31, wid = tidb >> 5;

    int v = 0;
    if (i < n) {
        v = g_counts[i];
        g_dinv[i] = rsqrtf((float)(v + 1));   // +1 self loop
        g_counts[i] = 0;                      // restore invariant for replay
    }
    int x = v;
#pragma unroll
    for (int o = 1; o < 32; o <<= 1) {
        int t = __shfl_up_sync(0xFFFFFFFFu, x, o);
        if (lane >= o) x += t;
    }
    if (lane == 31) wsum[wid] = x;
    __syncthreads();
    if (wid == 0) {
        int s = (lane < 16) ? wsum[lane] : 0;
#pragma unroll
        for (int o = 1; o < 16; o <<= 1) {
            int t = __shfl_up_sync(0xFFFFFFFFu, s, o);
            if (lane >= o) s += t;
        }
        if (lane < 16) wsum[lane] = s;
    }
    __syncthreads();
    int wbase = (wid > 0) ? wsum[wid - 1] : 0;
    int total = wsum[15];                     // block aggregate

    if (tidb == 0) {
        int run = 0;
        if (b == 0) {
            *(volatile unsigned long long*)&g_status[0] =
                (2ULL << 32) | (unsigned)total;
        } else {
            *(volatile unsigned long long*)&g_status[b] =
                (1ULL << 32) | (unsigned)total;
            int j = b - 1;
            while (true) {
                unsigned long long s =
                    *(volatile unsigned long long*)&g_status[j];
                unsigned st = (unsigned)(s >> 32);
                if (st == 0) continue;        // predecessor not published yet
                run += (int)(unsigned)s;
                if (st == 2u) break;          // hit an inclusive prefix
                j--;
            }
            *(volatile unsigned long long*)&g_status[b] =
                (2ULL << 32) | (unsigned)(run + total);
        }
        sbase = run;
    }
    __syncthreads();
    int base = sbase;
    if (i < n) {
        int val = base + wbase + x - v;       // FIX: include warp base
        g_rowptr[i] = val;
        g_cursor[i] = val;
    }
    if (b == nb - 1 && tidb == 0) g_rowptr[n] = base + total;   // = E
}

__global__ void k_scatter(const int* __restrict__ ei, int E) {
    int e = blockIdx.x * blockDim.x + threadIdx.x;
    if (e < E) {
        int s = ei[e];
        int d = ei[E + e];
        int pos = atomicAdd(&g_cursor[d], 1);
        float norm = g_dinv[s] * g_dinv[d];
        ((int2*)g_adj4)[pos] = make_int2(s, __float_as_int(norm));
    }
}

// ---------------- tensor-core GEMM: Hh[N,96] = X[N,96] @ W[96,96] ----------
// 2-pass compensated HMMA: acc += Xhi*Whi + Xhi*Wlo (fp32 accum).
// block: 256 threads (8 warps), TM=64 rows, 4 blocks/SM (52KB smem).
// warp w -> m-tile w&3, n-tiles (w>>2)*3 + {0,1,2} of 16x16.
__global__ __launch_bounds__(256) void k_gemm(int n, int layer) {
    extern __shared__ __align__(16) __half sm[];
    __half* Whi = sm;                       // hi+lo contiguous
    __half* Wlo = Whi + 96 * LDH;
    __half* Xhi = Whi + 2 * 96 * LDH;
    float*  Os  = (float*)Whi;              // overlay W region after compute

    int tid = threadIdx.x;
    int n0 = blockIdx.x * TM;
    int rows = min(TM, n - n0);

    // stage W hi+lo: straight uint4 copy (no conversions)
    {
        const uint4* s = (const uint4*)g_Whl[layer];
        uint4* d = (uint4*)Whi;
        for (int i = tid; i < (2 * 96 * LDH) / 8; i += 256) d[i] = s[i];
    }
    // stage X: row-wise uint4 copies (no conversions)
    {
        const uint4 zz = make_uint4(0, 0, 0, 0);
        for (int i = tid; i < TM * 12; i += 256) {
            int r = i / 12, c = (i % 12) * 8;
            uint4 vh = zz;
            if (r < rows) vh = *(const uint4*)&g_Xhi[(size_t)(n0 + r) * 96 + c];
            *(uint4*)&Xhi[r * LDH + c] = vh;
        }
    }
    __syncthreads();

    int warp = tid >> 5;
    int mi = warp & 3;                      // m tile 0..3
    int ng = warp >> 2;                     // n group 0..1 -> tiles ng*3+{0,1,2}

    wmma::fragment<wmma::accumulator, 16, 16, 16, float> acc[3];
#pragma unroll
    for (int j = 0; j < 3; j++) wmma::fill_fragment(acc[j], 0.f);

#pragma unroll
    for (int k = 0; k < 96; k += 16) {
        wmma::fragment<wmma::matrix_a, 16, 16, 16, __half, wmma::row_major> ahi;
        wmma::load_matrix_sync(ahi, &Xhi[(mi * 16) * LDH + k], LDH);
#pragma unroll
        for (int j = 0; j < 3; j++) {
            int nn = (ng * 3 + j) * 16;
            wmma::fragment<wmma::matrix_b, 16, 16, 16, __half, wmma::row_major> bhi, blo;
            wmma::load_matrix_sync(bhi, &Whi[k * LDH + nn], LDH);
            wmma::load_matrix_sync(blo, &Wlo[k * LDH + nn], LDH);
            wmma::mma_sync(acc[j], ahi, bhi, acc[j]);
            wmma::mma_sync(acc[j], ahi, blo, acc[j]);
        }
    }
    __syncthreads();                        // W region no longer needed

#pragma unroll
    for (int j = 0; j < 3; j++) {
        int nn = (ng * 3 + j) * 16;
        wmma::store_matrix_sync(&Os[(mi * 16) * 96 + nn], acc[j], 96,
                                wmma::mem_row_major);
    }
    __syncthreads();

    union H4 { __half2 h2[4]; uint4 u; };
    for (int i = tid; i < TM * 12; i += 256) {   // 12 groups of 8 floats/row
        int r = i / 12, g = i % 12;
        if (r < rows) {
            const float* src = &Os[r * 96 + g * 8];
            H4 s;
            s.h2[0] = __floats2half2_rn(src[0], src[1]);
            s.h2[1] = __floats2half2_rn(src[2], src[3]);
            s.h2[2] = __floats2half2_rn(src[4], src[5]);
            s.h2[3] = __floats2half2_rn(src[6], src[7]);
            *(uint4*)&g_hh[(size_t)(n0 + r) * HP + g * 8] = s.u;
        }
    }
}

// ---------------- aggregation: one warp per node ---------------------------
// reads g_hh (fp16, 192B rows); dst_sel=0: writes fp16 g_Xhi (GEMM2 input),
// dst_sel=1: writes external fp32 out. lane L (<24) owns features 4L..4L+3.
__global__ __launch_bounds__(256) void k_agg(const float* __restrict__ bias,
                                             const float* __restrict__ aptr,
                                             float* __restrict__ outExt,
                                             int n, int do_prelu, int dst_sel,
                                             int reset_status) {
    if (reset_status && blockIdx.x == 0 && threadIdx.x < NSCANBLK)
        g_status[threadIdx.x] = 0ULL;         // for next replay's k_scan
    int warp = (blockIdx.x * blockDim.x + threadIdx.x) >> 5;
    int lane = threadIdx.x & 31;
    if (warp >= n) return;

    const __half* h = (const __half*)g_hh;
    bool active = lane < 24;
    const uint2 zz = make_uint2(0u, 0u);

    float dn = g_dinv[warp];
    float dn2 = dn * dn;

    uint2 su = active ? *(const uint2*)(h + (size_t)warp * HP + lane * 4) : zz;
    float2 sp0 = __half22float2(*(__half2*)&su.x);
    float2 sp1 = __half22float2(*(__half2*)&su.y);
    float a0 = sp0.x * dn2, a1 = sp0.y * dn2;
    float a2 = sp1.x * dn2, a3 = sp1.y * dn2;

    int e = g_rowptr[warp];
    int end = g_rowptr[warp + 1];
    const int2* adj = (const int2*)g_adj4;

    if ((e & 1) && e < end) {                 // align to int4 pairs
        int2 q = adj[e];
        float nn = __int_as_float(q.y);
        uint2 u = active ? *(const uint2*)(h + (size_t)q.x * HP + lane * 4) : zz;
        float2 p0 = __half22float2(*(__half2*)&u.x);
        float2 p1 = __half22float2(*(__half2*)&u.y);
        a0 = fmaf(p0.x, nn, a0); a1 = fmaf(p0.y, nn, a1);
        a2 = fmaf(p1.x, nn, a2); a3 = fmaf(p1.y, nn, a3);
        e++;
    }
    for (; e + 3 < end; e += 4) {             // 4 edges: 2 adj LDG.128 + 4 LDG.64
        int4 qa = *(const int4*)(adj + e);
        int4 qb = *(const int4*)(adj + e + 2);
        uint2 u0 = active ? *(const uint2*)(h + (size_t)qa.x * HP + lane * 4) : zz;
        uint2 u1 = active ? *(const uint2*)(h + (size_t)qa.z * HP + lane * 4) : zz;
        uint2 u2 = active ? *(const uint2*)(h + (size_t)qb.x * HP + lane * 4) : zz;
        uint2 u3 = active ? *(const uint2*)(h + (size_t)qb.z * HP + lane * 4) : zz;
        float n0 = __int_as_float(qa.y), n1 = __int_as_float(qa.w);
        float n2 = __int_as_float(qb.y), n3 = __int_as_float(qb.w);
        float2 p00 = __half22float2(*(__half2*)&u0.x);
        float2 p01 = __half22float2(*(__half2*)&u0.y);
        float2 p10 = __half22float2(*(__half2*)&u1.x);
        float2 p11 = __half22float2(*(__half2*)&u1.y);
        float2 p20 = __half22float2(*(__half2*)&u2.x);
        float2 p21 = __half22float2(*(__half2*)&u2.y);
        float2 p30 = __half22float2(*(__half2*)&u3.x);
        float2 p31 = __half22float2(*(__half2*)&u3.y);
        a0 = fmaf(p00.x, n0, a0); a1 = fmaf(p00.y, n0, a1);
        a2 = fmaf(p01.x, n0, a2); a3 = fmaf(p01.y, n0, a3);
        a0 = fmaf(p10.x, n1, a0); a1 = fmaf(p10.y, n1, a1);
        a2 = fmaf(p11.x, n1, a2); a3 = fmaf(p11.y, n1, a3);
        a0 = fmaf(p20.x, n2, a0); a1 = fmaf(p20.y, n2, a1);
        a2 = fmaf(p21.x, n2, a2); a3 = fmaf(p21.y, n2, a3);
        a0 = fmaf(p30.x, n3, a0); a1 = fmaf(p30.y, n3, a1);
        a2 = fmaf(p31.x, n3, a2); a3 = fmaf(p31.y, n3, a3);
    }
    for (; e + 1 < end; e += 2) {
        int4 q = *(const int4*)(adj + e);
        uint2 u0 = active ? *(const uint2*)(h + (size_t)q.x * HP + lane * 4) : zz;
        uint2 u1 = active ? *(const uint2*)(h + (size_t)q.z * HP + lane * 4) : zz;
        float n0 = __int_as_float(q.y), n1 = __int_as_float(q.w);
        float2 p00 = __half22float2(*(__half2*)&u0.x);
        float2 p01 = __half22float2(*(__half2*)&u0.y);
        float2 p10 = __half22float2(*(__half2*)&u1.x);
        float2 p11 = __half22float2(*(__half2*)&u1.y);
        a0 = fmaf(p00.x, n0, a0); a1 = fmaf(p00.y, n0, a1);
        a2 = fmaf(p01.x, n0, a2); a3 = fmaf(p01.y, n0, a3);
        a0 = fmaf(p10.x, n1, a0); a1 = fmaf(p10.y, n1, a1);
        a2 = fmaf(p11.x, n1, a2); a3 = fmaf(p11.y, n1, a3);
    }
    if (e < end) {
        int2 q = adj[e];
        float nn = __int_as_float(q.y);
        uint2 u = active ? *(const uint2*)(h + (size_t)q.x * HP + lane * 4) : zz;
        float2 p0 = __half22float2(*(__half2*)&u.x);
        float2 p1 = __half22float2(*(__half2*)&u.y);
        a0 = fmaf(p0.x, nn, a0); a1 = fmaf(p0.y, nn, a1);
        a2 = fmaf(p1.x, nn, a2); a3 = fmaf(p1.y, nn, a3);
    }

    if (active) {                             // features 4L..4L+3 valid
        float4 bb = ((const float4*)bias)[lane];
        a0 += bb.x; a1 += bb.y; a2 += bb.z; a3 += bb.w;
        if (do_prelu) {
            float a = aptr[0];
            a0 = (a0 > 0.f) ? a0 : a * a0;
            a1 = (a1 > 0.f) ? a1 : a * a1;
            a2 = (a2 > 0.f) ? a2 : a * a2;
            a3 = (a3 > 0.f) ? a3 : a * a3;
        }
        if (dst_sel) {
            ((float4*)(outExt + (size_t)warp * 96))[lane] =
                make_float4(a0, a1, a2, a3);
        } else {
            __half2 H0 = __floats2half2_rn(a0, a1);
            __half2 H1 = __floats2half2_rn(a2, a3);
            *(uint2*)&g_Xhi[(size_t)warp * 96 + lane * 4] =
                make_uint2(*(unsigned*)&H0, *(unsigned*)&H1);
        }
    }
}

// ---------------- launch ---------------------------------------------------
extern "C" void kernel_launch(void* const* d_in, const int* in_sizes, int n_in,
                              void* d_out, int out_size) {
    const float* x  = (const float*)d_in[0];
    const int*   ei = (const int*)d_in[1];      // int32! (JAX x64 disabled)
    const float* W1 = (const float*)d_in[2];
    const float* b1 = (const float*)d_in[3];
    const float* a1 = (const float*)d_in[4];
    const float* W2 = (const float*)d_in[5];
    const float* b2 = (const float*)d_in[6];
    float*       out = (float*)d_out;

    int N = in_sizes[0] / D;
    int E = in_sizes[1] / 2;

    int nscan = (N + SCAN_B - 1) / SCAN_B;
    int gemm_blocks = (N + TM - 1) / TM;
    int agg_blocks = (N * 32 + 255) / 256;
    int split_blocks = (N * D + 255) / 256;

    cudaFuncSetAttribute(k_gemm, cudaFuncAttributeMaxDynamicSharedMemorySize,
                         GEMM_SMEM_BYTES);

    // 1) split X/W to fp16 + degree histogram (fused)
    k_split<<<split_blocks, 256>>>(x, W1, W2, ei, N, E);
    // 2) GEMM1 (tensor cores)
    k_gemm<<<gemm_blocks, 256, GEMM_SMEM_BYTES>>>(N, 0);
    // 3) single-pass scan (dinv + rowptr + cursor, decoupled lookback)
    k_scan<<<nscan, SCAN_B>>>(N, nscan);
    // 4) scatter edges into CSR
    k_scatter<<<(E + 255) / 256, 256>>>(ei, E);
    // 5) layer-1 aggregate + PReLU -> g_Xhi (also resets lookback statuses)
    k_agg<<<agg_blocks, 256>>>(b1, a1, out, N, 1, 0, 1);
    // 6) GEMM2
    k_gemm<<<gemm_blocks, 256, GEMM_SMEM_BYTES>>>(N, 1);
    // 7) layer-2 aggregate -> out
    k_agg<<<agg_blocks, 256>>>(b2, a1, out, N, 0, 1, 0);
}